// round 12
// baseline (speedup 1.0000x reference)
#include <cuda_runtime.h>
#include <cuda_fp16.h>
#include <cstdint>

#define DIM 128
#define TM  64        // rows per gemm tile
#define TILES_PER 3   // tiles per gemm CTA
#define PREP 128      // prep CTAs (compute Mc)
#define SCAT 64       // scatter CTAs

// ---------------------------------------------------------------------------
// Global scratch (no allocations allowed)
// ---------------------------------------------------------------------------
__device__ __align__(16) __half g_Bc[DIM * DIM];   // Mc = Wo@Wv, fp16, [n][k]
// Coverage bitmap; all-zero at every launch entry (zero-init + scatter clears
// its own partition each launch after scanning).
__device__ uint32_t g_maskbits[4096];
// Monotonic counters (never reset; launch index derived via ticket/count).
__device__ uint32_t g_donem;   // prep completions    (+PREP  per launch)
__device__ uint32_t g_scatm;   // scatter completions (+SCAT  per launch)
__device__ uint32_t g_gstart;  // gemm CTA starts     (+ngemm per launch)
__device__ uint32_t g_fin;     // gemm CTA finishes   (+ngemm per launch)

__device__ __forceinline__ uint32_t smem_u32(const void* p) {
    uint32_t a;
    asm("{ .reg .u64 t; cvta.to.shared.u64 t, %1; cvt.u32.u64 %0, t; }" : "=r"(a) : "l"(p));
    return a;
}
__device__ __forceinline__ uint32_t ld_acquire(const uint32_t* p) {
    uint32_t v;
    asm volatile("ld.acquire.gpu.u32 %0, [%1];" : "=r"(v) : "l"(p) : "memory");
    return v;
}
__device__ __forceinline__ void ldsm4(uint32_t& r0, uint32_t& r1, uint32_t& r2,
                                      uint32_t& r3, uint32_t a) {
    asm volatile("ldmatrix.sync.aligned.m8n8.x4.shared.b16 {%0,%1,%2,%3}, [%4];"
                 : "=r"(r0), "=r"(r1), "=r"(r2), "=r"(r3) : "r"(a));
}
__device__ __forceinline__ void mma16816(float* c, const uint32_t* a, const uint32_t* b) {
    asm volatile(
        "mma.sync.aligned.m16n8k16.row.col.f32.f16.f16.f32 "
        "{%0,%1,%2,%3},{%4,%5,%6,%7},{%8,%9},{%0,%1,%2,%3};"
        : "+f"(c[0]), "+f"(c[1]), "+f"(c[2]), "+f"(c[3])
        : "r"(a[0]), "r"(a[1]), "r"(a[2]), "r"(a[3]), "r"(b[0]), "r"(b[1]));
}
__device__ __forceinline__ void cp_async16(uint32_t dst, const void* src) {
    asm volatile("cp.async.ca.shared.global [%0], [%1], 16;" :: "r"(dst), "l"(src)
                 : "memory");
}
__device__ __forceinline__ void bm_or4(uint32_t* bm, int4 v) {
    atomicOr(&bm[v.x >> 5], 1u << (v.x & 31));
    atomicOr(&bm[v.y >> 5], 1u << (v.y & 31));
    atomicOr(&bm[v.z >> 5], 1u << (v.z & 31));
    atomicOr(&bm[v.w >> 5], 1u << (v.w & 31));
}

// ---------------------------------------------------------------------------
#define ROWB   272
#define AS_OFF 0
#define BS_OFF 17408
#define BO_OFF 52224
#define SMEM_SZ 52736

// Load one 64-row A tile (fp32 -> fp16) into padded smem rows.
__device__ __forceinline__ void load_A(const float* __restrict__ X,
                                       unsigned char* sm, int m0, int Nn, int tid) {
#pragma unroll
    for (int it = 0; it < 8; ++it) {
        int f = tid + 256 * it;
        int r = f >> 5;
        int c4 = (f & 31) << 2;
        float4 v = make_float4(0.f, 0.f, 0.f, 0.f);
        int grow = m0 + r;
        if (grow < Nn) v = *(const float4*)&X[grow * DIM + c4];
        __half2 h01 = __float22half2_rn(make_float2(v.x, v.y));
        __half2 h23 = __float22half2_rn(make_float2(v.z, v.w));
        uint2 w;
        w.x = *(uint32_t*)&h01; w.y = *(uint32_t*)&h23;
        *(uint2*)(sm + AS_OFF + r * ROWB + c4 * 2) = w;
    }
}

// ---------------------------------------------------------------------------
// Single fused kernel:
//   blocks [0, PREP)         : Mc row -> g_Bc, signal g_donem
//   blocks [PREP, PREP+SCAT) : bitmap scatter (MLP-4) -> barrier -> scan own
//                              partition; uncovered rows (expected none):
//                              wait all gemm done, overwrite with bo. Clears
//                              partition for replay.
//   blocks [PREP+SCAT, ...)  : GEMM, TILES_PER tiles per CTA, B loaded once;
//                              next-tile A-fill overlaps current epilogue.
// ---------------------------------------------------------------------------
__global__ __launch_bounds__(256, 3) void fused_kernel(
    const float* __restrict__ X, const float* __restrict__ Wo,
    const float* __restrict__ Wv, const float* __restrict__ bo,
    const int* __restrict__ tgt, float* __restrict__ out, int Nn, int E) {
    extern __shared__ unsigned char sm[];
    const int tid = threadIdx.x;
    const uint32_t ngemm = gridDim.x - PREP - SCAT;

    if (blockIdx.x < PREP) {
        // ---------------- prep path: one row of Mc ----------------
        float* WoS = (float*)sm;              // [128]
        float* red = (float*)sm + 128;        // [8*136]
        const int b = blockIdx.x;
        if (tid < DIM) WoS[tid] = Wo[b * DIM + tid];
        __syncthreads();

        const int j4 = (tid & 31) * 4;
        const int kl = tid >> 5;
        float a0 = 0.f, a1 = 0.f, a2 = 0.f, a3 = 0.f;
#pragma unroll
        for (int kk = 0; kk < 16; ++kk) {
            int k = kl * 16 + kk;
            float4 v = *(const float4*)&Wv[k * DIM + j4];
            float w = WoS[k];
            a0 = fmaf(w, v.x, a0);
            a1 = fmaf(w, v.y, a1);
            a2 = fmaf(w, v.z, a2);
            a3 = fmaf(w, v.w, a3);
        }
        *(float4*)&red[kl * 136 + j4] = make_float4(a0, a1, a2, a3);
        __syncthreads();
        if (tid < DIM) {
            float s = 0.f;
#pragma unroll
            for (int kl2 = 0; kl2 < 8; ++kl2) s += red[kl2 * 136 + tid];
            g_Bc[b * DIM + tid] = __float2half_rn(s);
        }
        __syncthreads();
        if (tid == 0) {
            __threadfence();
            atomicAdd(&g_donem, 1u);
        }
        return;
    }

    if (blockIdx.x < PREP + SCAT) {
        // ---------------- scatter + self-service fixup ----------------
        uint32_t* bm = (uint32_t*)sm;                 // [nwords]
        __shared__ uint32_t sR;                       // launch index
        const int bs = blockIdx.x - PREP;
        const int nwords = (Nn + 31) >> 5;
        for (int i = tid; i < nwords; i += 256) bm[i] = 0;
        __syncthreads();

        const int E4 = E >> 2;
        const int4* tgt4 = (const int4*)tgt;
        const int stride = SCAT * 256;
        int i = bs * 256 + tid;
        for (; i + 3 * stride < E4; i += 4 * stride) {   // MLP-4 batched loads
            int4 v0 = __ldcs(&tgt4[i]);
            int4 v1 = __ldcs(&tgt4[i + stride]);
            int4 v2 = __ldcs(&tgt4[i + 2 * stride]);
            int4 v3 = __ldcs(&tgt4[i + 3 * stride]);
            bm_or4(bm, v0); bm_or4(bm, v1); bm_or4(bm, v2); bm_or4(bm, v3);
        }
        for (; i < E4; i += stride) bm_or4(bm, __ldcs(&tgt4[i]));
        if (bs == 0 && tid < (E & 3)) {   // tail (<4 edges)
            int n = tgt[E4 * 4 + tid];
            atomicOr(&g_maskbits[n >> 5], 1u << (n & 31));
        }
        __syncthreads();
        for (int i2 = tid; i2 < nwords; i2 += 256) {
            uint32_t w = bm[i2];
            if (w) atomicOr(&g_maskbits[i2], w);
        }
        // Barrier among the SCAT scatter CTAs (monotonic ticket).
        __threadfence();
        if (tid == 0) {
            uint32_t t = atomicAdd(&g_scatm, 1u);
            uint32_t R = t / SCAT;
            sR = R;
            uint32_t target = (R + 1u) * SCAT;
            while (ld_acquire(&g_scatm) < target) { }
        }
        __syncthreads();   // sR visible; merged bitmap complete

        // Scan own exclusive partition for uncovered nodes; clear for replay.
        const int part = (nwords + SCAT - 1) / SCAT;
        const int lo = bs * part;
        const int hi = min(lo + part, nwords);
        const uint32_t fin_target = (sR + 1u) * ngemm;
        for (int w = lo + tid; w < hi; w += 256) {
            uint32_t v = __ldcg(&g_maskbits[w]);
            __stcg(&g_maskbits[w], 0u);            // replay invariant
            uint32_t missing = ~v;
            if (!missing) continue;
            int base = w << 5;
            while (missing) {
                int bit = __ffs(missing) - 1;
                missing &= missing - 1;
                int n = base + bit;
                if (n < Nn) {
                    // Rare path: wait for ALL gemm CTAs, overwrite row with bo.
                    while (ld_acquire(&g_fin) < fin_target) { }
                    float4* dst = (float4*)&out[n * DIM];
                    const float4* src = (const float4*)bo;
#pragma unroll
                    for (int c = 0; c < 32; ++c) dst[c] = src[c];
                }
            }
        }
        return;
    }

    // ---------------- gemm path: TILES_PER tiles, B loaded once -------------
    const int warp = tid >> 5, lane = tid & 31;
    const int wm = warp & 1, wn = warp >> 1;
    const int gid = lane >> 2, tig = lane & 3;
    const uint32_t smb = smem_u32(sm);
    const int gidx = blockIdx.x - PREP - SCAT;
    const int ntiles = (Nn + TM - 1) / TM;

    // Tile-0 A load overlaps the prep wait.
    load_A(X, sm, gidx * TM, Nn, tid);
    if (tid < DIM) ((float*)(sm + BO_OFF))[tid] = bo[tid];

    // Wait for this launch's prep completion (monotonic ticket -> launch idx).
    if (tid == 0) {
        uint32_t t = atomicAdd(&g_gstart, 1u);
        uint32_t target = (t / ngemm + 1u) * PREP;
        while (ld_acquire(&g_donem) < target) { }
    }
    __syncthreads();   // covers A-tile visibility + flag

    // B: cp.async g_Bc (now ready, hot in L2) into padded smem rows — ONCE.
#pragma unroll
    for (int i = tid; i < 2048; i += 256) {
        int r = i >> 4, seg = i & 15;
        cp_async16(smb + BS_OFF + r * ROWB + seg * 16, (const char*)g_Bc + i * 16);
    }
    asm volatile("cp.async.commit_group;" ::: "memory");
    asm volatile("cp.async.wait_group 0;" ::: "memory");
    __syncthreads();

    const uint32_t lrow = lane & 15;
    const uint32_t lk16 = (lane >> 4) * 16;
    const float* boS = (const float*)(sm + BO_OFF);

    int tile = gidx;
    for (int tt = 0;;) {
        const int m0 = tile * TM;

        float acc[2][4][4];
#pragma unroll
        for (int mt = 0; mt < 2; ++mt)
#pragma unroll
            for (int nt = 0; nt < 4; ++nt)
#pragma unroll
                for (int q = 0; q < 4; ++q) acc[mt][nt][q] = 0.f;

#pragma unroll
        for (int kk = 0; kk < 8; ++kk) {
            uint32_t af[2][4];
#pragma unroll
            for (int mt = 0; mt < 2; ++mt) {
                uint32_t a = smb + AS_OFF + (wm * 32 + mt * 16 + lrow) * ROWB + kk * 32 + lk16;
                ldsm4(af[mt][0], af[mt][1], af[mt][2], af[mt][3], a);
            }
            uint32_t bf[4][2];
#pragma unroll
            for (int np = 0; np < 2; ++np) {
                uint32_t a = smb + BS_OFF + (wn * 32 + np * 16 + lrow) * ROWB + kk * 32 + lk16;
                uint32_t r0, r1, r2, r3;
                ldsm4(r0, r1, r2, r3, a);
                bf[2 * np][0] = r0; bf[2 * np + 1][0] = r1;
                bf[2 * np][1] = r2; bf[2 * np + 1][1] = r3;
            }
#pragma unroll
            for (int mt = 0; mt < 2; ++mt)
#pragma unroll
                for (int nt = 0; nt < 4; ++nt)
                    mma16816(acc[mt][nt], af[mt], bf[nt]);
        }

        __syncthreads();   // all As reads done -> As may be refilled

        // Next-tile A fill overlaps this tile's epilogue stores.
        ++tt;
        const int ntile = tile + (int)ngemm;
        const bool more = (tt < TILES_PER) && (ntile < ntiles);
        if (more) load_A(X, sm, ntile * TM, Nn, tid);

        // Unconditional epilogue: out = acc + bo.
#pragma unroll
        for (int mt = 0; mt < 2; ++mt) {
            int r0 = wm * 32 + mt * 16 + gid;
            int ga = m0 + r0, gb = ga + 8;
#pragma unroll
            for (int nt = 0; nt < 4; ++nt) {
                int col = wn * 32 + nt * 8 + 2 * tig;
                float b0 = boS[col], b1 = boS[col + 1];
                if (ga < Nn)
                    *(float2*)&out[ga * DIM + col] = make_float2(
                        acc[mt][nt][0] + b0, acc[mt][nt][1] + b1);
                if (gb < Nn)
                    *(float2*)&out[gb * DIM + col] = make_float2(
                        acc[mt][nt][2] + b0, acc[mt][nt][3] + b1);
            }
        }

        if (!more) break;
        __syncthreads();   // As refill complete before next mainloop
        tile = ntile;
    }

    if (tid == 0) {
        __threadfence();
        atomicAdd(&g_fin, 1u);
    }
}

// ---------------------------------------------------------------------------
extern "C" void kernel_launch(void* const* d_in, const int* in_sizes, int n_in,
                              void* d_out, int out_size) {
    const float* x          = (const float*)d_in[0];
    const int*   edge_index = (const int*)d_in[1];
    const float* Wv         = (const float*)d_in[5];
    const float* Wo         = (const float*)d_in[7];
    const float* bo         = (const float*)d_in[8];
    float*       out        = (float*)d_out;

    const int N = in_sizes[0] / DIM;
    const int E = in_sizes[1] / 2;
    const int* tgt = edge_index + E;
    const int ntiles = (N + TM - 1) / TM;
    const int gemm_blks = (ntiles + TILES_PER - 1) / TILES_PER;

    cudaFuncSetAttribute(fused_kernel, cudaFuncAttributeMaxDynamicSharedMemorySize,
                         SMEM_SZ);

    fused_kernel<<<PREP + SCAT + gemm_blks, 256, SMEM_SZ>>>(x, Wo, Wv, bo, tgt,
                                                            out, N, E);
}